// round 1
// baseline (speedup 1.0000x reference)
#include <cuda_runtime.h>

#define DIMX   1024
#define HEADS  16
#define DH     64
#define INNER  1024
#define NQKV   3072
#define BATCH  2
#define SEQ    2048
#define ROWS   (BATCH*SEQ)      /* 4096 */
#define BHT    (BATCH*HEADS)    /* 32   */
#define QSCALE 0.125f
#define LN_EPS 1e-5f

/* ------------ scratch (no allocations allowed) ------------ */
__device__ float g_xn [ROWS*DIMX];
__device__ float g_qkv[(size_t)ROWS*NQKV];
__device__ float g_q  [(size_t)BHT*SEQ*DH];
__device__ float g_k  [(size_t)BHT*SEQ*DH];
__device__ float g_kt [(size_t)BHT*DH*SEQ];
__device__ float g_v  [(size_t)BHT*SEQ*DH];
__device__ float g_att[(size_t)ROWS*INNER];

/* ---------------- LayerNorm: one block per row ---------------- */
__global__ void ln_kernel(const float* __restrict__ x,
                          const float* __restrict__ w,
                          const float* __restrict__ b,
                          float* __restrict__ out) {
    int row = blockIdx.x;
    int tid = threadIdx.x;                    // 256 threads, 4 floats each
    const float* xr = x + (size_t)row * DIMX;
    float4 xv = *(const float4*)(xr + tid*4);
    float s  = xv.x + xv.y + xv.z + xv.w;
    float ss = xv.x*xv.x + xv.y*xv.y + xv.z*xv.z + xv.w*xv.w;
    __shared__ float red1[8], red2[8];
    int lane = tid & 31, wid = tid >> 5;
    #pragma unroll
    for (int o = 16; o; o >>= 1) {
        s  += __shfl_xor_sync(0xffffffffu, s,  o);
        ss += __shfl_xor_sync(0xffffffffu, ss, o);
    }
    if (lane == 0) { red1[wid] = s; red2[wid] = ss; }
    __syncthreads();
    if (tid == 0) {
        float ts = 0.f, tss = 0.f;
        #pragma unroll
        for (int i = 0; i < 8; i++) { ts += red1[i]; tss += red2[i]; }
        float mean = ts * (1.0f/DIMX);
        float var  = tss * (1.0f/DIMX) - mean*mean;
        red1[0] = mean;
        red2[0] = rsqrtf(var + LN_EPS);
    }
    __syncthreads();
    float mean = red1[0], rstd = red2[0];
    float4 wv = *(const float4*)(w + tid*4);
    float4 bv = *(const float4*)(b + tid*4);
    float4 o;
    o.x = (xv.x-mean)*rstd*wv.x + bv.x;
    o.y = (xv.y-mean)*rstd*wv.y + bv.y;
    o.z = (xv.z-mean)*rstd*wv.z + bv.z;
    o.w = (xv.w-mean)*rstd*wv.w + bv.w;
    *(float4*)(out + (size_t)row*DIMX + tid*4) = o;
}

/* ---------------- classic 128x128x8 SGEMM, 256 threads ---------------- */
__global__ void sgemm128(const float* __restrict__ A,
                         const float* __restrict__ Bm,
                         float* __restrict__ C,
                         int M, int Nc, int K) {
    __shared__ float As[8][128];
    __shared__ float Bs[8][128];
    int tid = threadIdx.x;
    const float* Ab = A  + (size_t)blockIdx.y * 128 * K;
    const float* Bb = Bm + blockIdx.x * 128;
    float acc[8][8];
    #pragma unroll
    for (int i = 0; i < 8; i++)
        #pragma unroll
        for (int j = 0; j < 8; j++) acc[i][j] = 0.f;
    int arow = tid >> 1, acol = (tid & 1) << 2;
    int brow = tid >> 5, bcol = (tid & 31) << 2;
    int ty = tid >> 4, tx = tid & 15;
    for (int k0 = 0; k0 < K; k0 += 8) {
        float4 a4 = *(const float4*)(Ab + (size_t)arow*K + k0 + acol);
        As[acol+0][arow] = a4.x; As[acol+1][arow] = a4.y;
        As[acol+2][arow] = a4.z; As[acol+3][arow] = a4.w;
        *(float4*)(&Bs[brow][bcol]) = *(const float4*)(Bb + (size_t)(k0+brow)*Nc + bcol);
        __syncthreads();
        #pragma unroll
        for (int k = 0; k < 8; k++) {
            float4 a0 = *(const float4*)(&As[k][ty*8]);
            float4 a1 = *(const float4*)(&As[k][ty*8+4]);
            float4 b0 = *(const float4*)(&Bs[k][tx*8]);
            float4 b1 = *(const float4*)(&Bs[k][tx*8+4]);
            float ra[8] = {a0.x,a0.y,a0.z,a0.w,a1.x,a1.y,a1.z,a1.w};
            float rb[8] = {b0.x,b0.y,b0.z,b0.w,b1.x,b1.y,b1.z,b1.w};
            #pragma unroll
            for (int i = 0; i < 8; i++)
                #pragma unroll
                for (int j = 0; j < 8; j++)
                    acc[i][j] += ra[i]*rb[j];
        }
        __syncthreads();
    }
    float* Cb = C + ((size_t)blockIdx.y*128 + ty*8)*Nc + blockIdx.x*128 + tx*8;
    #pragma unroll
    for (int i = 0; i < 8; i++) {
        *(float4*)(Cb + (size_t)i*Nc)     = make_float4(acc[i][0],acc[i][1],acc[i][2],acc[i][3]);
        *(float4*)(Cb + (size_t)i*Nc + 4) = make_float4(acc[i][4],acc[i][5],acc[i][6],acc[i][7]);
    }
}

/* -------- RoPE + head split: qkv [rows,3072] -> q/k/v [bh][n][d] -------- */
__global__ void rope_kernel(const float* __restrict__ qkv,
                            const float* __restrict__ pos,
                            float* __restrict__ q,
                            float* __restrict__ k,
                            float* __restrict__ v) {
    int idx = blockIdx.x * blockDim.x + threadIdx.x;   // over B*N*H*DH
    int d = idx & (DH-1);
    int h = (idx >> 6) & (HEADS-1);
    int n = (idx >> 10) & (SEQ-1);
    int b = idx >> 21;
    size_t row = (size_t)b*SEQ + n;
    const float* qr = qkv + row*NQKV;
    float p = pos[n*DH + d];
    float c, sn;
    sincosf(p, &sn, &c);
    int dp = (d < DH/2) ? d + DH/2 : d - DH/2;
    float sgn = (d < DH/2) ? -1.f : 1.f;
    float qv  = qr[h*DH + d],           qp = qr[h*DH + dp];
    float kvv = qr[INNER + h*DH + d],   kp = qr[INNER + h*DH + dp];
    size_t o = ((size_t)(b*HEADS + h)*SEQ + n)*DH + d;
    q[o] = (qv*c + sgn*qp*sn) * QSCALE;
    k[o] = kvv*c + sgn*kp*sn;
    v[o] = qr[2*INNER + h*DH + d];
}

/* -------- K transpose: [bh][n][d] -> [bh][d][n] (smem 32x32 tiles) -------- */
__global__ void transpose_k(const float* __restrict__ kin,
                            float* __restrict__ kout) {
    __shared__ float t[32][33];
    int bh = blockIdx.z;
    int n0 = blockIdx.x * 32, d0 = blockIdx.y * 32;
    int x = threadIdx.x, y = threadIdx.y;              // 32 x 8
    #pragma unroll
    for (int yy = y; yy < 32; yy += 8)
        t[yy][x] = kin[((size_t)bh*SEQ + n0 + yy)*DH + d0 + x];
    __syncthreads();
    #pragma unroll
    for (int yy = y; yy < 32; yy += 8)
        kout[((size_t)bh*DH + d0 + yy)*SEQ + n0 + x] = t[x][yy];
}

/* -------- causal flash attention, 64x64 tiles, fp32, online softmax -------- */
__global__ void attn_kernel(const float* __restrict__ Q,
                            const float* __restrict__ KT,   /* [bh][d][n] */
                            const float* __restrict__ V,
                            float* __restrict__ Out) {      /* [b][n][h*d] */
    __shared__ float sQ [64*64];
    __shared__ float sKS[64*64];   /* K^T tile, reused for P */
    __shared__ float sV [64*64];
    int tid = threadIdx.x;
    int qt = blockIdx.x, bh = blockIdx.y;
    int q0 = qt * 64;
    const float* Qb = Q + ((size_t)bh*SEQ + q0)*DH;
    #pragma unroll
    for (int it = 0; it < 4; it++) {
        int f = tid + it*256;
        int r = f >> 4, c4 = (f & 15) << 2;
        *(float4*)(sQ + r*64 + c4) = *(const float4*)(Qb + r*DH + c4);
    }
    int ty = tid >> 4, tx = tid & 15;
    int i0 = ty*4, j0 = tx*4;
    float m[4], l[4];
    float4 acc[4];
    #pragma unroll
    for (int ii = 0; ii < 4; ii++) {
        m[ii] = -1e30f; l[ii] = 0.f;
        acc[ii] = make_float4(0.f,0.f,0.f,0.f);
    }

    for (int kt = 0; kt <= qt; kt++) {
        __syncthreads();                       /* sKS/sV reuse safe */
        const float* KTb = KT + (size_t)bh*DH*SEQ + kt*64;
        const float* Vb  = V  + ((size_t)bh*SEQ + kt*64)*DH;
        #pragma unroll
        for (int it = 0; it < 4; it++) {
            int f = tid + it*256;
            int r = f >> 4, c4 = (f & 15) << 2;
            *(float4*)(sKS + r*64 + c4) = *(const float4*)(KTb + (size_t)r*SEQ + c4);
            *(float4*)(sV  + r*64 + c4) = *(const float4*)(Vb  + r*DH  + c4);
        }
        __syncthreads();

        /* S = Q K^T : 4x4 per thread */
        float s[4][4];
        #pragma unroll
        for (int ii = 0; ii < 4; ii++)
            #pragma unroll
            for (int jj = 0; jj < 4; jj++) s[ii][jj] = 0.f;
        #pragma unroll
        for (int kd = 0; kd < 64; kd += 4) {
            float qa[4][4];
            #pragma unroll
            for (int ii = 0; ii < 4; ii++) {
                float4 qv = *(const float4*)(sQ + (i0+ii)*64 + kd);
                qa[ii][0]=qv.x; qa[ii][1]=qv.y; qa[ii][2]=qv.z; qa[ii][3]=qv.w;
            }
            #pragma unroll
            for (int u = 0; u < 4; u++) {
                float4 kv = *(const float4*)(sKS + (kd+u)*64 + j0);
                #pragma unroll
                for (int ii = 0; ii < 4; ii++) {
                    float qs = qa[ii][u];
                    s[ii][0] += qs*kv.x; s[ii][1] += qs*kv.y;
                    s[ii][2] += qs*kv.z; s[ii][3] += qs*kv.w;
                }
            }
        }
        if (kt == qt) {
            #pragma unroll
            for (int ii = 0; ii < 4; ii++)
                #pragma unroll
                for (int jj = 0; jj < 4; jj++)
                    if (j0+jj > i0+ii) s[ii][jj] = -1e30f;
        }

        /* online softmax: row state in registers, shfl over the 16-lane row group */
        float alpha[4];
        #pragma unroll
        for (int ii = 0; ii < 4; ii++) {
            float rm = fmaxf(fmaxf(s[ii][0], s[ii][1]), fmaxf(s[ii][2], s[ii][3]));
            #pragma unroll
            for (int off = 8; off; off >>= 1)
                rm = fmaxf(rm, __shfl_xor_sync(0xffffffffu, rm, off));
            float mnew = fmaxf(m[ii], rm);
            alpha[ii] = __expf(m[ii] - mnew);
            m[ii] = mnew;
            float rs = 0.f;
            #pragma unroll
            for (int jj = 0; jj < 4; jj++) {
                s[ii][jj] = __expf(s[ii][jj] - mnew);
                rs += s[ii][jj];
            }
            #pragma unroll
            for (int off = 8; off; off >>= 1)
                rs += __shfl_xor_sync(0xffffffffu, rs, off);
            l[ii] = l[ii]*alpha[ii] + rs;
            acc[ii].x *= alpha[ii]; acc[ii].y *= alpha[ii];
            acc[ii].z *= alpha[ii]; acc[ii].w *= alpha[ii];
        }
        __syncthreads();                       /* K reads done; reuse sKS for P */
        #pragma unroll
        for (int ii = 0; ii < 4; ii++)
            *(float4*)(sKS + (i0+ii)*64 + j0) =
                make_float4(s[ii][0], s[ii][1], s[ii][2], s[ii][3]);
        __syncthreads();

        /* O += P @ V */
        #pragma unroll 8
        for (int j = 0; j < 64; j++) {
            float4 vv = *(const float4*)(sV + j*64 + j0);
            #pragma unroll
            for (int ii = 0; ii < 4; ii++) {
                float p = sKS[(i0+ii)*64 + j];
                acc[ii].x += p*vv.x; acc[ii].y += p*vv.y;
                acc[ii].z += p*vv.z; acc[ii].w += p*vv.w;
            }
        }
    }

    int b = bh >> 4, h = bh & 15;
    #pragma unroll
    for (int ii = 0; ii < 4; ii++) {
        float inv = 1.0f / l[ii];
        float4 o = acc[ii];
        o.x *= inv; o.y *= inv; o.z *= inv; o.w *= inv;
        *(float4*)(Out + ((size_t)(b*SEQ + q0 + i0 + ii))*INNER + h*DH + j0) = o;
    }
}

/* ---------------------------- launch ---------------------------- */
extern "C" void kernel_launch(void* const* d_in, const int* in_sizes, int n_in,
                              void* d_out, int out_size) {
    const float* x    = (const float*)d_in[0];
    const float* pos  = (const float*)d_in[1];
    const float* lnw  = (const float*)d_in[2];
    const float* lnb  = (const float*)d_in[3];
    const float* wqkv = (const float*)d_in[4];
    const float* wout = (const float*)d_in[5];
    float* out = (float*)d_out;

    float *xn, *qkv, *q, *k, *kt, *v, *att;
    cudaGetSymbolAddress((void**)&xn,  g_xn);
    cudaGetSymbolAddress((void**)&qkv, g_qkv);
    cudaGetSymbolAddress((void**)&q,   g_q);
    cudaGetSymbolAddress((void**)&k,   g_k);
    cudaGetSymbolAddress((void**)&kt,  g_kt);
    cudaGetSymbolAddress((void**)&v,   g_v);
    cudaGetSymbolAddress((void**)&att, g_att);

    ln_kernel<<<ROWS, 256>>>(x, lnw, lnb, xn);
    sgemm128<<<dim3(NQKV/128, ROWS/128), 256>>>(xn, wqkv, qkv, ROWS, NQKV, DIMX);
    rope_kernel<<<(BATCH*SEQ*HEADS*DH)/256, 256>>>(qkv, pos, q, k, v);
    transpose_k<<<dim3(SEQ/32, DH/32, BHT), dim3(32, 8)>>>(k, kt);
    attn_kernel<<<dim3(SEQ/64, BHT), 256>>>(q, kt, v, att);
    sgemm128<<<dim3(INNER/128, ROWS/128), 256>>>(att, wout, out, ROWS, INNER, DIMX);
}

// round 2
// speedup vs baseline: 1.8961x; 1.8961x over previous
#include <cuda_runtime.h>

#define DIMX   1024
#define HEADS  16
#define DH     64
#define INNER  1024
#define NQKV   3072
#define BATCH  2
#define SEQ    2048
#define ROWS   (BATCH*SEQ)      /* 4096 */
#define BHT    (BATCH*HEADS)    /* 32   */
#define QSCALE 0.125f
#define LN_EPS 1e-5f

/* ------------ scratch (no allocations allowed) ------------ */
__device__ float g_xn [ROWS*DIMX];
__device__ float g_qkv[(size_t)ROWS*NQKV];
__device__ float g_q  [(size_t)BHT*SEQ*DH];
__device__ float g_k  [(size_t)BHT*SEQ*DH];
__device__ float g_v  [(size_t)BHT*SEQ*DH];
__device__ float g_att[(size_t)ROWS*INNER];

/* ---------------- helpers ---------------- */
__device__ __forceinline__ unsigned f2tf(float x) {
    unsigned u;
    asm("cvt.rna.tf32.f32 %0, %1;" : "=r"(u) : "f"(x));
    return u;
}
__device__ __forceinline__ void mma_tf32(float4& c,
                                         unsigned a0, unsigned a1, unsigned a2, unsigned a3,
                                         unsigned b0, unsigned b1) {
    asm("mma.sync.aligned.m16n8k8.row.col.f32.tf32.tf32.f32 "
        "{%0,%1,%2,%3}, {%4,%5,%6,%7}, {%8,%9}, {%0,%1,%2,%3};"
        : "+f"(c.x), "+f"(c.y), "+f"(c.z), "+f"(c.w)
        : "r"(a0), "r"(a1), "r"(a2), "r"(a3), "r"(b0), "r"(b1));
}

/* ---------------- LayerNorm: one block per row ---------------- */
__global__ void ln_kernel(const float* __restrict__ x,
                          const float* __restrict__ w,
                          const float* __restrict__ b,
                          float* __restrict__ out) {
    int row = blockIdx.x;
    int tid = threadIdx.x;
    const float* xr = x + (size_t)row * DIMX;
    float4 xv = *(const float4*)(xr + tid*4);
    float s  = xv.x + xv.y + xv.z + xv.w;
    float ss = xv.x*xv.x + xv.y*xv.y + xv.z*xv.z + xv.w*xv.w;
    __shared__ float red1[8], red2[8];
    int lane = tid & 31, wid = tid >> 5;
    #pragma unroll
    for (int o = 16; o; o >>= 1) {
        s  += __shfl_xor_sync(0xffffffffu, s,  o);
        ss += __shfl_xor_sync(0xffffffffu, ss, o);
    }
    if (lane == 0) { red1[wid] = s; red2[wid] = ss; }
    __syncthreads();
    if (tid == 0) {
        float ts = 0.f, tss = 0.f;
        #pragma unroll
        for (int i = 0; i < 8; i++) { ts += red1[i]; tss += red2[i]; }
        float mean = ts * (1.0f/DIMX);
        float var  = tss * (1.0f/DIMX) - mean*mean;
        red1[0] = mean;
        red2[0] = rsqrtf(var + LN_EPS);
    }
    __syncthreads();
    float mean = red1[0], rstd = red2[0];
    float4 wv = *(const float4*)(w + tid*4);
    float4 bv = *(const float4*)(b + tid*4);
    float4 o;
    o.x = (xv.x-mean)*rstd*wv.x + bv.x;
    o.y = (xv.y-mean)*rstd*wv.y + bv.y;
    o.z = (xv.z-mean)*rstd*wv.z + bv.z;
    o.w = (xv.w-mean)*rstd*wv.w + bv.w;
    *(float4*)(out + (size_t)row*DIMX + tid*4) = o;
}

/* ---------------- tf32 tensor-core GEMM: 128x128x32, 256 thr ---------------- */
__global__ void __launch_bounds__(256) gemm_tf32(const float* __restrict__ A,
                                                 const float* __restrict__ B,
                                                 float* __restrict__ C,
                                                 int N, int K) {
    __shared__ float sA[128*36];    /* [row][k] stride 36: bank = 4g+t = lane */
    __shared__ float sB[32*132];    /* [k][n]  stride 132 */
    int tid = threadIdx.x, lane = tid & 31, w = tid >> 5;
    int g = lane >> 2, t = lane & 3;
    int wm = w >> 2, wn = w & 3;                /* warp tile 64 x 32 */
    const float* Ab = A + (size_t)blockIdx.y * 128 * K;
    const float* Bb = B + blockIdx.x * 128;
    float4 acc[4][4];
    #pragma unroll
    for (int i = 0; i < 4; i++)
        #pragma unroll
        for (int j = 0; j < 4; j++) acc[i][j] = make_float4(0.f,0.f,0.f,0.f);
    int arow = tid >> 1, ah = tid & 1;
    int bk = tid >> 3,  bj = tid & 7;

    for (int k0 = 0; k0 < K; k0 += 32) {
        __syncthreads();
        #pragma unroll
        for (int i = 0; i < 4; i++) {
            float4 a = *(const float4*)(Ab + (size_t)arow*K + k0 + ah*16 + 4*i);
            float4 o;
            o.x = __uint_as_float(f2tf(a.x)); o.y = __uint_as_float(f2tf(a.y));
            o.z = __uint_as_float(f2tf(a.z)); o.w = __uint_as_float(f2tf(a.w));
            *(float4*)(sA + arow*36 + ah*16 + 4*i) = o;
        }
        #pragma unroll
        for (int i = 0; i < 4; i++) {
            float4 b = *(const float4*)(Bb + (size_t)(k0 + bk)*N + bj*16 + 4*i);
            float4 o;
            o.x = __uint_as_float(f2tf(b.x)); o.y = __uint_as_float(f2tf(b.y));
            o.z = __uint_as_float(f2tf(b.z)); o.w = __uint_as_float(f2tf(b.w));
            *(float4*)(sB + bk*132 + bj*16 + 4*i) = o;
        }
        __syncthreads();
        #pragma unroll
        for (int ks = 0; ks < 4; ks++) {
            unsigned a[4][4], bf[4][2];
            #pragma unroll
            for (int mt = 0; mt < 4; mt++) {
                int r = wm*64 + mt*16 + g;
                a[mt][0] = __float_as_uint(sA[r*36     + ks*8 + t]);
                a[mt][1] = __float_as_uint(sA[(r+8)*36 + ks*8 + t]);
                a[mt][2] = __float_as_uint(sA[r*36     + ks*8 + t + 4]);
                a[mt][3] = __float_as_uint(sA[(r+8)*36 + ks*8 + t + 4]);
            }
            #pragma unroll
            for (int nt = 0; nt < 4; nt++) {
                int c = wn*32 + nt*8 + g;
                bf[nt][0] = __float_as_uint(sB[(ks*8 + t)*132     + c]);
                bf[nt][1] = __float_as_uint(sB[(ks*8 + t + 4)*132 + c]);
            }
            #pragma unroll
            for (int mt = 0; mt < 4; mt++)
                #pragma unroll
                for (int nt = 0; nt < 4; nt++)
                    mma_tf32(acc[mt][nt], a[mt][0],a[mt][1],a[mt][2],a[mt][3],
                             bf[nt][0], bf[nt][1]);
        }
    }
    #pragma unroll
    for (int mt = 0; mt < 4; mt++) {
        #pragma unroll
        for (int nt = 0; nt < 4; nt++) {
            int r = blockIdx.y*128 + wm*64 + mt*16 + g;
            int c = blockIdx.x*128 + wn*32 + nt*8 + 2*t;
            *(float2*)(C + (size_t)r*N + c)     = make_float2(acc[mt][nt].x, acc[mt][nt].y);
            *(float2*)(C + (size_t)(r+8)*N + c) = make_float2(acc[mt][nt].z, acc[mt][nt].w);
        }
    }
}

/* -------- RoPE + head split: qkv [rows,3072] -> q/k/v [bh][n][d] -------- */
__global__ void rope_kernel(const float* __restrict__ qkv,
                            const float* __restrict__ pos,
                            float* __restrict__ q,
                            float* __restrict__ k,
                            float* __restrict__ v) {
    int idx = blockIdx.x * blockDim.x + threadIdx.x;
    int d = idx & (DH-1);
    int h = (idx >> 6) & (HEADS-1);
    int n = (idx >> 10) & (SEQ-1);
    int b = idx >> 21;
    size_t row = (size_t)b*SEQ + n;
    const float* qr = qkv + row*NQKV;
    float p = pos[n*DH + d];
    float c, sn;
    sincosf(p, &sn, &c);
    int dp = (d < DH/2) ? d + DH/2 : d - DH/2;
    float sgn = (d < DH/2) ? -1.f : 1.f;
    float qv  = qr[h*DH + d],           qp = qr[h*DH + dp];
    float kvv = qr[INNER + h*DH + d],   kp = qr[INNER + h*DH + dp];
    size_t o = ((size_t)(b*HEADS + h)*SEQ + n)*DH + d;
    q[o] = (qv*c + sgn*qp*sn) * QSCALE;
    k[o] = kvv*c + sgn*kp*sn;
    v[o] = qr[2*INNER + h*DH + d];
}

/* -------- causal flash attention, tf32 MMA, 64 q-rows/block, 4 warps -------- */
__global__ void __launch_bounds__(128) attn_tc(const float* __restrict__ Q,
                                               const float* __restrict__ K,
                                               const float* __restrict__ V,
                                               float* __restrict__ Out) {
    __shared__ float sQK[64*68];    /* Q staging, then K tiles [key][d] */
    __shared__ float sV [64*68];    /* V transposed [d][key] */
    int tid = threadIdx.x;
    int lane = tid & 31, wq = tid >> 5;
    int g = lane >> 2, t = lane & 3;
    int qt = blockIdx.x, bh = blockIdx.y;
    int q0 = qt * 64;

    /* stage Q (tf32) */
    {
        const float* Qb = Q + ((size_t)bh*SEQ + q0)*DH;
        int row = tid >> 1, h = tid & 1;
        const float* src = Qb + row*DH + h*32;
        float* dst = sQK + row*68 + h*32;
        #pragma unroll
        for (int i = 0; i < 8; i++) {
            float4 xv = *(const float4*)(src + 4*i);
            float4 o;
            o.x = __uint_as_float(f2tf(xv.x)); o.y = __uint_as_float(f2tf(xv.y));
            o.z = __uint_as_float(f2tf(xv.z)); o.w = __uint_as_float(f2tf(xv.w));
            *(float4*)(dst + 4*i) = o;
        }
    }
    __syncthreads();
    /* Q fragments -> registers (persist across key tiles) */
    unsigned qa[8][4];
    int r0 = wq*16 + g;
    #pragma unroll
    for (int ks = 0; ks < 8; ks++) {
        qa[ks][0] = __float_as_uint(sQK[r0*68     + ks*8 + t]);
        qa[ks][1] = __float_as_uint(sQK[(r0+8)*68 + ks*8 + t]);
        qa[ks][2] = __float_as_uint(sQK[r0*68     + ks*8 + t + 4]);
        qa[ks][3] = __float_as_uint(sQK[(r0+8)*68 + ks*8 + t + 4]);
    }

    float m0 = -1e30f, m1 = -1e30f, l0 = 0.f, l1 = 0.f;
    float4 o[8];
    #pragma unroll
    for (int i = 0; i < 8; i++) o[i] = make_float4(0.f,0.f,0.f,0.f);

    for (int kt = 0; kt <= qt; kt++) {
        __syncthreads();
        /* load K tile [key][d], V tile transposed [d][key], both tf32 */
        {
            const float* Kb = K + ((size_t)bh*SEQ + kt*64)*DH;
            const float* Vb = V + ((size_t)bh*SEQ + kt*64)*DH;
            int row = tid >> 1, h = tid & 1;
            #pragma unroll
            for (int i = 0; i < 8; i++) {
                float4 kv = *(const float4*)(Kb + row*DH + h*32 + 4*i);
                float4 ko;
                ko.x = __uint_as_float(f2tf(kv.x)); ko.y = __uint_as_float(f2tf(kv.y));
                ko.z = __uint_as_float(f2tf(kv.z)); ko.w = __uint_as_float(f2tf(kv.w));
                *(float4*)(sQK + row*68 + h*32 + 4*i) = ko;
                float4 vv = *(const float4*)(Vb + row*DH + h*32 + 4*i);
                int d = h*32 + 4*i;
                sV[(d+0)*68 + row] = __uint_as_float(f2tf(vv.x));
                sV[(d+1)*68 + row] = __uint_as_float(f2tf(vv.y));
                sV[(d+2)*68 + row] = __uint_as_float(f2tf(vv.z));
                sV[(d+3)*68 + row] = __uint_as_float(f2tf(vv.w));
            }
        }
        __syncthreads();

        /* S = Q K^T : 8 n-tiles of m16n8, k = 64 in 8 steps */
        float4 s[8];
        #pragma unroll
        for (int i = 0; i < 8; i++) s[i] = make_float4(0.f,0.f,0.f,0.f);
        #pragma unroll
        for (int ks = 0; ks < 8; ks++) {
            #pragma unroll
            for (int nt = 0; nt < 8; nt++) {
                unsigned b0 = __float_as_uint(sQK[(nt*8+g)*68 + ks*8 + t]);
                unsigned b1 = __float_as_uint(sQK[(nt*8+g)*68 + ks*8 + t + 4]);
                mma_tf32(s[nt], qa[ks][0], qa[ks][1], qa[ks][2], qa[ks][3], b0, b1);
            }
        }
        if (kt == qt) {
            #pragma unroll
            for (int nt = 0; nt < 8; nt++) {
                int c0 = nt*8 + 2*t;
                if (c0     > r0)   s[nt].x = -1e30f;
                if (c0 + 1 > r0)   s[nt].y = -1e30f;
                if (c0     > r0+8) s[nt].z = -1e30f;
                if (c0 + 1 > r0+8) s[nt].w = -1e30f;
            }
        }

        /* online softmax (rows g and g+8), reduce over quad via shfl */
        float rm0 = -1e30f, rm1 = -1e30f;
        #pragma unroll
        for (int nt = 0; nt < 8; nt++) {
            rm0 = fmaxf(rm0, fmaxf(s[nt].x, s[nt].y));
            rm1 = fmaxf(rm1, fmaxf(s[nt].z, s[nt].w));
        }
        rm0 = fmaxf(rm0, __shfl_xor_sync(0xffffffffu, rm0, 1));
        rm0 = fmaxf(rm0, __shfl_xor_sync(0xffffffffu, rm0, 2));
        rm1 = fmaxf(rm1, __shfl_xor_sync(0xffffffffu, rm1, 1));
        rm1 = fmaxf(rm1, __shfl_xor_sync(0xffffffffu, rm1, 2));
        float mn0 = fmaxf(m0, rm0), mn1 = fmaxf(m1, rm1);
        float al0 = __expf(m0 - mn0), al1 = __expf(m1 - mn1);
        m0 = mn0; m1 = mn1;
        float rs0 = 0.f, rs1 = 0.f;
        #pragma unroll
        for (int nt = 0; nt < 8; nt++) {
            s[nt].x = __expf(s[nt].x - mn0);
            s[nt].y = __expf(s[nt].y - mn0);
            s[nt].z = __expf(s[nt].z - mn1);
            s[nt].w = __expf(s[nt].w - mn1);
            rs0 += s[nt].x + s[nt].y;
            rs1 += s[nt].z + s[nt].w;
        }
        rs0 += __shfl_xor_sync(0xffffffffu, rs0, 1);
        rs0 += __shfl_xor_sync(0xffffffffu, rs0, 2);
        rs1 += __shfl_xor_sync(0xffffffffu, rs1, 1);
        rs1 += __shfl_xor_sync(0xffffffffu, rs1, 2);
        l0 = l0*al0 + rs0;
        l1 = l1*al1 + rs1;
        #pragma unroll
        for (int dn = 0; dn < 8; dn++) {
            o[dn].x *= al0; o[dn].y *= al0;
            o[dn].z *= al1; o[dn].w *= al1;
        }

        /* P (C-layout) -> A fragments via shfl remap, then O += P V */
        int base = lane & 28;
        int src1 = base | (t >> 1);
        int src2 = src1 + 2;
        bool odd = (t & 1);
        #pragma unroll
        for (int s8 = 0; s8 < 8; s8++) {
            unsigned p0 = f2tf(s[s8].x), p1 = f2tf(s[s8].y);
            unsigned p2 = f2tf(s[s8].z), p3 = f2tf(s[s8].w);
            unsigned q00 = __shfl_sync(0xffffffffu, p0, src1);
            unsigned q01 = __shfl_sync(0xffffffffu, p1, src1);
            unsigned q10 = __shfl_sync(0xffffffffu, p2, src1);
            unsigned q11 = __shfl_sync(0xffffffffu, p3, src1);
            unsigned q20 = __shfl_sync(0xffffffffu, p0, src2);
            unsigned q21 = __shfl_sync(0xffffffffu, p1, src2);
            unsigned q30 = __shfl_sync(0xffffffffu, p2, src2);
            unsigned q31 = __shfl_sync(0xffffffffu, p3, src2);
            unsigned a0 = odd ? q01 : q00;
            unsigned a1 = odd ? q11 : q10;
            unsigned a2 = odd ? q21 : q20;
            unsigned a3 = odd ? q31 : q30;
            #pragma unroll
            for (int dn = 0; dn < 8; dn++) {
                unsigned b0 = __float_as_uint(sV[(dn*8 + g)*68 + s8*8 + t]);
                unsigned b1 = __float_as_uint(sV[(dn*8 + g)*68 + s8*8 + t + 4]);
                mma_tf32(o[dn], a0, a1, a2, a3, b0, b1);
            }
        }
    }

    /* epilogue: divide by l, write [b][n][h*d] */
    float inv0 = 1.f / l0, inv1 = 1.f / l1;
    int b = bh >> 4, h = bh & 15;
    float* ob0 = Out + ((size_t)(b*SEQ + q0 + r0))*INNER + h*DH;
    float* ob1 = Out + ((size_t)(b*SEQ + q0 + r0 + 8))*INNER + h*DH;
    #pragma unroll
    for (int dn = 0; dn < 8; dn++) {
        int c = dn*8 + 2*t;
        *(float2*)(ob0 + c) = make_float2(o[dn].x*inv0, o[dn].y*inv0);
        *(float2*)(ob1 + c) = make_float2(o[dn].z*inv1, o[dn].w*inv1);
    }
}

/* ---------------------------- launch ---------------------------- */
extern "C" void kernel_launch(void* const* d_in, const int* in_sizes, int n_in,
                              void* d_out, int out_size) {
    const float* x    = (const float*)d_in[0];
    const float* pos  = (const float*)d_in[1];
    const float* lnw  = (const float*)d_in[2];
    const float* lnb  = (const float*)d_in[3];
    const float* wqkv = (const float*)d_in[4];
    const float* wout = (const float*)d_in[5];
    float* out = (float*)d_out;

    float *xn, *qkv, *q, *k, *v, *att;
    cudaGetSymbolAddress((void**)&xn,  g_xn);
    cudaGetSymbolAddress((void**)&qkv, g_qkv);
    cudaGetSymbolAddress((void**)&q,   g_q);
    cudaGetSymbolAddress((void**)&k,   g_k);
    cudaGetSymbolAddress((void**)&v,   g_v);
    cudaGetSymbolAddress((void**)&att, g_att);

    ln_kernel<<<ROWS, 256>>>(x, lnw, lnb, xn);
    gemm_tf32<<<dim3(NQKV/128, ROWS/128), 256>>>(xn, wqkv, qkv, NQKV, DIMX);
    rope_kernel<<<(BATCH*SEQ*HEADS*DH)/256, 256>>>(qkv, pos, q, k, v);
    attn_tc<<<dim3(SEQ/64, BHT), 128>>>(q, k, v, att);
    gemm_tf32<<<dim3(INNER/128, ROWS/128), 256>>>(att, wout, out, INNER, DIMX);
}

// round 3
// speedup vs baseline: 3.1215x; 1.6463x over previous
#include <cuda_runtime.h>

#define DIMX   1024
#define HEADS  16
#define DH     64
#define INNER  1024
#define NQKV   3072
#define BATCH  2
#define SEQ    2048
#define ROWS   (BATCH*SEQ)      /* 4096 */
#define BHT    (BATCH*HEADS)    /* 32   */
#define QSCALE 0.125f
#define LN_EPS 1e-5f

/* ------------ scratch (no allocations allowed) ------------ */
__device__ float g_xn  [ROWS*DIMX];
__device__ float g_qkv [(size_t)ROWS*NQKV];
__device__ float g_q   [(size_t)BHT*SEQ*DH];
__device__ float g_k   [(size_t)BHT*SEQ*DH];
__device__ float g_v   [(size_t)BHT*SEQ*DH];
__device__ float g_att [(size_t)ROWS*INNER];
__device__ float g_wqr [(size_t)DIMX*NQKV];
__device__ float g_wor [(size_t)INNER*DIMX];

/* ---------------- helpers ---------------- */
__device__ __forceinline__ unsigned f2tf(float x) {
    unsigned u;
    asm("cvt.rna.tf32.f32 %0, %1;" : "=r"(u) : "f"(x));
    return u;
}
__device__ __forceinline__ float f2tff(float x) {
    return __uint_as_float(f2tf(x));
}
__device__ __forceinline__ void mma_tf32(float4& c,
                                         unsigned a0, unsigned a1, unsigned a2, unsigned a3,
                                         unsigned b0, unsigned b1) {
    asm("mma.sync.aligned.m16n8k8.row.col.f32.tf32.tf32.f32 "
        "{%0,%1,%2,%3}, {%4,%5,%6,%7}, {%8,%9}, {%0,%1,%2,%3};"
        : "+f"(c.x), "+f"(c.y), "+f"(c.z), "+f"(c.w)
        : "r"(a0), "r"(a1), "r"(a2), "r"(a3), "r"(b0), "r"(b1));
}
__device__ __forceinline__ void cpa16(float* dst, const float* src) {
    unsigned d = (unsigned)__cvta_generic_to_shared(dst);
    asm volatile("cp.async.cg.shared.global [%0], [%1], 16;" :: "r"(d), "l"(src));
}
__device__ __forceinline__ void cpa_commit_waitall() {
    asm volatile("cp.async.commit_group;\ncp.async.wait_group 0;" ::: "memory");
}

/* ------------ pre-round weights to tf32 ------------ */
__global__ void roundw(const float* __restrict__ wqkv,
                       const float* __restrict__ wout,
                       float* __restrict__ oq, float* __restrict__ oo) {
    int i = blockIdx.x*blockDim.x + threadIdx.x;      /* float4 index */
    const int NQ = (DIMX*NQKV)/4;
    float4 v;
    if (i < NQ) {
        v = ((const float4*)wqkv)[i];
        v.x=f2tff(v.x); v.y=f2tff(v.y); v.z=f2tff(v.z); v.w=f2tff(v.w);
        ((float4*)oq)[i] = v;
    } else {
        int j = i - NQ;
        v = ((const float4*)wout)[j];
        v.x=f2tff(v.x); v.y=f2tff(v.y); v.z=f2tff(v.z); v.w=f2tff(v.w);
        ((float4*)oo)[j] = v;
    }
}

/* ---------------- LayerNorm: one block per row, tf32-rounded out --------- */
__global__ void ln_kernel(const float* __restrict__ x,
                          const float* __restrict__ w,
                          const float* __restrict__ b,
                          float* __restrict__ out) {
    int row = blockIdx.x;
    int tid = threadIdx.x;
    const float* xr = x + (size_t)row * DIMX;
    float4 xv = *(const float4*)(xr + tid*4);
    float s  = xv.x + xv.y + xv.z + xv.w;
    float ss = xv.x*xv.x + xv.y*xv.y + xv.z*xv.z + xv.w*xv.w;
    __shared__ float red1[8], red2[8];
    int lane = tid & 31, wid = tid >> 5;
    #pragma unroll
    for (int o = 16; o; o >>= 1) {
        s  += __shfl_xor_sync(0xffffffffu, s,  o);
        ss += __shfl_xor_sync(0xffffffffu, ss, o);
    }
    if (lane == 0) { red1[wid] = s; red2[wid] = ss; }
    __syncthreads();
    if (tid == 0) {
        float ts = 0.f, tss = 0.f;
        #pragma unroll
        for (int i = 0; i < 8; i++) { ts += red1[i]; tss += red2[i]; }
        float mean = ts * (1.0f/DIMX);
        float var  = tss * (1.0f/DIMX) - mean*mean;
        red1[0] = mean;
        red2[0] = rsqrtf(var + LN_EPS);
    }
    __syncthreads();
    float mean = red1[0], rstd = red2[0];
    float4 wv = *(const float4*)(w + tid*4);
    float4 bv = *(const float4*)(b + tid*4);
    float4 o;
    o.x = f2tff((xv.x-mean)*rstd*wv.x + bv.x);
    o.y = f2tff((xv.y-mean)*rstd*wv.y + bv.y);
    o.z = f2tff((xv.z-mean)*rstd*wv.z + bv.z);
    o.w = f2tff((xv.w-mean)*rstd*wv.w + bv.w);
    *(float4*)(out + (size_t)row*DIMX + tid*4) = o;
}

/* ------- tf32 GEMM: 128x128, k-slab 16, cp.async double-buffer, 256 thr ------- */
__global__ void __launch_bounds__(256) gemm_tf32(const float* __restrict__ A,
                                                 const float* __restrict__ B,
                                                 float* __restrict__ C,
                                                 int N, int K) {
    __shared__ float sA[2][128*20];    /* [row][k] stride 20: bank 20g+t distinct */
    __shared__ float sB[2][16*136];    /* [k][n]  stride 136: bank 8t+g distinct */
    int tid = threadIdx.x, lane = tid & 31, w = tid >> 5;
    int g = lane >> 2, t = lane & 3;
    int wm = w >> 2, wn = w & 3;                /* warp tile 64 x 32 */
    const float* Ab = A + (size_t)blockIdx.y * 128 * K;
    const float* Bb = B + blockIdx.x * 128;
    float4 acc[4][4];
    #pragma unroll
    for (int i = 0; i < 4; i++)
        #pragma unroll
        for (int j = 0; j < 4; j++) acc[i][j] = make_float4(0.f,0.f,0.f,0.f);

    const int nslab = K / 16;

    /* prologue: slab 0 */
    {
        #pragma unroll
        for (int c = 0; c < 2; c++) {
            int chunk = tid + c*256;
            int r = chunk >> 2, seg = chunk & 3;
            cpa16(&sA[0][r*20 + seg*4], Ab + (size_t)r*K + seg*4);
        }
        #pragma unroll
        for (int c = 0; c < 2; c++) {
            int chunk = tid + c*256;
            int r = chunk >> 5, seg = chunk & 31;
            cpa16(&sB[0][r*136 + seg*4], Bb + (size_t)r*N + seg*4);
        }
        asm volatile("cp.async.commit_group;" ::: "memory");
    }

    for (int sidx = 0; sidx < nslab; sidx++) {
        int buf = sidx & 1;
        asm volatile("cp.async.wait_group 0;" ::: "memory");
        __syncthreads();
        if (sidx + 1 < nslab) {
            int k0 = (sidx+1)*16, nb = buf ^ 1;
            #pragma unroll
            for (int c = 0; c < 2; c++) {
                int chunk = tid + c*256;
                int r = chunk >> 2, seg = chunk & 3;
                cpa16(&sA[nb][r*20 + seg*4], Ab + (size_t)r*K + k0 + seg*4);
            }
            #pragma unroll
            for (int c = 0; c < 2; c++) {
                int chunk = tid + c*256;
                int r = chunk >> 5, seg = chunk & 31;
                cpa16(&sB[nb][r*136 + seg*4], Bb + (size_t)(k0 + r)*N + seg*4);
            }
            asm volatile("cp.async.commit_group;" ::: "memory");
        }
        #pragma unroll
        for (int ks = 0; ks < 2; ks++) {
            unsigned a[4][4], bf[4][2];
            #pragma unroll
            for (int mt = 0; mt < 4; mt++) {
                int r = wm*64 + mt*16 + g;
                a[mt][0] = __float_as_uint(sA[buf][r*20     + ks*8 + t]);
                a[mt][1] = __float_as_uint(sA[buf][(r+8)*20 + ks*8 + t]);
                a[mt][2] = __float_as_uint(sA[buf][r*20     + ks*8 + t + 4]);
                a[mt][3] = __float_as_uint(sA[buf][(r+8)*20 + ks*8 + t + 4]);
            }
            #pragma unroll
            for (int nt = 0; nt < 4; nt++) {
                int c = wn*32 + nt*8 + g;
                bf[nt][0] = __float_as_uint(sB[buf][(ks*8 + t)*136     + c]);
                bf[nt][1] = __float_as_uint(sB[buf][(ks*8 + t + 4)*136 + c]);
            }
            #pragma unroll
            for (int mt = 0; mt < 4; mt++)
                #pragma unroll
                for (int nt = 0; nt < 4; nt++)
                    mma_tf32(acc[mt][nt], a[mt][0],a[mt][1],a[mt][2],a[mt][3],
                             bf[nt][0], bf[nt][1]);
        }
    }
    #pragma unroll
    for (int mt = 0; mt < 4; mt++) {
        #pragma unroll
        for (int nt = 0; nt < 4; nt++) {
            int r = blockIdx.y*128 + wm*64 + mt*16 + g;
            int c = blockIdx.x*128 + wn*32 + nt*8 + 2*t;
            *(float2*)(C + (size_t)r*N + c)     = make_float2(acc[mt][nt].x, acc[mt][nt].y);
            *(float2*)(C + (size_t)(r+8)*N + c) = make_float2(acc[mt][nt].z, acc[mt][nt].w);
        }
    }
}

/* -------- RoPE + head split: qkv [rows,3072] -> q/k/v [bh][n][d], tf32 ------ */
__global__ void rope_kernel(const float* __restrict__ qkv,
                            const float* __restrict__ pos,
                            float* __restrict__ q,
                            float* __restrict__ k,
                            float* __restrict__ v) {
    int idx = blockIdx.x * blockDim.x + threadIdx.x;
    int d = idx & (DH-1);
    int h = (idx >> 6) & (HEADS-1);
    int n = (idx >> 10) & (SEQ-1);
    int b = idx >> 21;
    size_t row = (size_t)b*SEQ + n;
    const float* qr = qkv + row*NQKV;
    float p = pos[n*DH + d];
    float c, sn;
    sincosf(p, &sn, &c);
    int dp = (d < DH/2) ? d + DH/2 : d - DH/2;
    float sgn = (d < DH/2) ? -1.f : 1.f;
    float qv  = qr[h*DH + d],           qp = qr[h*DH + dp];
    float kvv = qr[INNER + h*DH + d],   kp = qr[INNER + h*DH + dp];
    size_t o = ((size_t)(b*HEADS + h)*SEQ + n)*DH + d;
    q[o] = f2tff((qv*c + sgn*qp*sn) * QSCALE);
    k[o] = f2tff(kvv*c + sgn*kp*sn);
    v[o] = f2tff(qr[2*INNER + h*DH + d]);
}

/* ---- causal flash attention: 128 q-rows/block, 4 warps x 32 rows (2 m-tiles) ---- */
__global__ void __launch_bounds__(128, 1) attn_tc(const float* __restrict__ Q,
                                                  const float* __restrict__ K,
                                                  const float* __restrict__ V,
                                                  float* __restrict__ Out) {
    __shared__ float sK[64*72];    /* Q staging, then K tiles [key][d] stride 72 */
    __shared__ float sV[64*72];    /* V tiles [key][d] stride 72 (natural layout) */
    int tid = threadIdx.x;
    int lane = tid & 31, wq = tid >> 5;
    int g = lane >> 2, t = lane & 3;
    int qt = gridDim.x - 1 - blockIdx.x;      /* heavy blocks first */
    int bh = blockIdx.y;
    int q0 = qt * 128;
    const float* Qb = Q + ((size_t)bh*SEQ + q0)*DH;
    const float* Kb = K + (size_t)bh*SEQ*DH;
    const float* Vb = V + (size_t)bh*SEQ*DH;

    /* stage Q in 2 halves through sK; extract A-fragments to registers */
    unsigned qa[2][8][4];
    #pragma unroll
    for (int half = 0; half < 2; half++) {
        #pragma unroll
        for (int c = 0; c < 8; c++) {
            int chunk = tid + c*128;
            int row = chunk >> 4, seg = chunk & 15;
            cpa16(sK + row*72 + seg*4, Qb + (size_t)(half*64 + row)*DH + seg*4);
        }
        cpa_commit_waitall();
        __syncthreads();
        if ((wq >> 1) == half) {
            int lrb = (wq & 1) * 32;
            #pragma unroll
            for (int mt = 0; mt < 2; mt++) {
                int lr = lrb + mt*16 + g;
                #pragma unroll
                for (int ks = 0; ks < 8; ks++) {
                    qa[mt][ks][0] = __float_as_uint(sK[lr*72     + ks*8 + t]);
                    qa[mt][ks][1] = __float_as_uint(sK[(lr+8)*72 + ks*8 + t]);
                    qa[mt][ks][2] = __float_as_uint(sK[lr*72     + ks*8 + t + 4]);
                    qa[mt][ks][3] = __float_as_uint(sK[(lr+8)*72 + ks*8 + t + 4]);
                }
            }
        }
        __syncthreads();
    }

    float m[2][2], l[2][2];
    float4 o[2][8];
    #pragma unroll
    for (int mt = 0; mt < 2; mt++) {
        m[mt][0] = m[mt][1] = -1e30f;
        l[mt][0] = l[mt][1] = 0.f;
        #pragma unroll
        for (int i = 0; i < 8; i++) o[mt][i] = make_float4(0.f,0.f,0.f,0.f);
    }

    int warpRow0 = q0 + wq*32;
    int ntiles = 2*qt + 2;
    for (int kt = 0; kt < ntiles; kt++) {
        __syncthreads();
        #pragma unroll
        for (int c = 0; c < 8; c++) {
            int chunk = tid + c*128;
            int row = chunk >> 4, seg = chunk & 15;
            cpa16(sK + row*72 + seg*4, Kb + (size_t)(kt*64 + row)*DH + seg*4);
            cpa16(sV + row*72 + seg*4, Vb + (size_t)(kt*64 + row)*DH + seg*4);
        }
        cpa_commit_waitall();
        __syncthreads();

        /* S = Q K^T */
        float4 s[2][8];
        #pragma unroll
        for (int mt = 0; mt < 2; mt++)
            #pragma unroll
            for (int i = 0; i < 8; i++) s[mt][i] = make_float4(0.f,0.f,0.f,0.f);
        #pragma unroll
        for (int ks = 0; ks < 8; ks++) {
            unsigned bf[8][2];
            #pragma unroll
            for (int nt = 0; nt < 8; nt++) {
                bf[nt][0] = __float_as_uint(sK[(nt*8+g)*72 + ks*8 + t]);
                bf[nt][1] = __float_as_uint(sK[(nt*8+g)*72 + ks*8 + t + 4]);
            }
            #pragma unroll
            for (int mt = 0; mt < 2; mt++)
                #pragma unroll
                for (int nt = 0; nt < 8; nt++)
                    mma_tf32(s[mt][nt], qa[mt][ks][0], qa[mt][ks][1],
                             qa[mt][ks][2], qa[mt][ks][3], bf[nt][0], bf[nt][1]);
        }

        /* causal mask (only near the diagonal) */
        if (kt*64 + 63 > warpRow0) {
            #pragma unroll
            for (int mt = 0; mt < 2; mt++) {
                int r0g = warpRow0 + mt*16 + g;
                #pragma unroll
                for (int nt = 0; nt < 8; nt++) {
                    int c0 = kt*64 + nt*8 + 2*t;
                    if (c0     > r0g)   s[mt][nt].x = -1e30f;
                    if (c0 + 1 > r0g)   s[mt][nt].y = -1e30f;
                    if (c0     > r0g+8) s[mt][nt].z = -1e30f;
                    if (c0 + 1 > r0g+8) s[mt][nt].w = -1e30f;
                }
            }
        }

        /* online softmax per m-tile */
        #pragma unroll
        for (int mt = 0; mt < 2; mt++) {
            float rm0 = -1e30f, rm1 = -1e30f;
            #pragma unroll
            for (int nt = 0; nt < 8; nt++) {
                rm0 = fmaxf(rm0, fmaxf(s[mt][nt].x, s[mt][nt].y));
                rm1 = fmaxf(rm1, fmaxf(s[mt][nt].z, s[mt][nt].w));
            }
            rm0 = fmaxf(rm0, __shfl_xor_sync(0xffffffffu, rm0, 1));
            rm0 = fmaxf(rm0, __shfl_xor_sync(0xffffffffu, rm0, 2));
            rm1 = fmaxf(rm1, __shfl_xor_sync(0xffffffffu, rm1, 1));
            rm1 = fmaxf(rm1, __shfl_xor_sync(0xffffffffu, rm1, 2));
            float mn0 = fmaxf(m[mt][0], rm0), mn1 = fmaxf(m[mt][1], rm1);
            float al0 = __expf(m[mt][0] - mn0), al1 = __expf(m[mt][1] - mn1);
            m[mt][0] = mn0; m[mt][1] = mn1;
            float rs0 = 0.f, rs1 = 0.f;
            #pragma unroll
            for (int nt = 0; nt < 8; nt++) {
                s[mt][nt].x = __expf(s[mt][nt].x - mn0);
                s[mt][nt].y = __expf(s[mt][nt].y - mn0);
                s[mt][nt].z = __expf(s[mt][nt].z - mn1);
                s[mt][nt].w = __expf(s[mt][nt].w - mn1);
                rs0 += s[mt][nt].x + s[mt][nt].y;
                rs1 += s[mt][nt].z + s[mt][nt].w;
            }
            rs0 += __shfl_xor_sync(0xffffffffu, rs0, 1);
            rs0 += __shfl_xor_sync(0xffffffffu, rs0, 2);
            rs1 += __shfl_xor_sync(0xffffffffu, rs1, 1);
            rs1 += __shfl_xor_sync(0xffffffffu, rs1, 2);
            l[mt][0] = l[mt][0]*al0 + rs0;
            l[mt][1] = l[mt][1]*al1 + rs1;
            #pragma unroll
            for (int dn = 0; dn < 8; dn++) {
                o[mt][dn].x *= al0; o[mt][dn].y *= al0;
                o[mt][dn].z *= al1; o[mt][dn].w *= al1;
            }
        }

        /* P remap (C-layout -> A fragments via shfl) and O += P V */
        int base = lane & 28;
        int src1 = base | (t >> 1);
        int src2 = src1 + 2;
        bool odd = (t & 1);
        #pragma unroll
        for (int s8 = 0; s8 < 8; s8++) {
            unsigned pa[2][4];
            #pragma unroll
            for (int mt = 0; mt < 2; mt++) {
                unsigned p0 = f2tf(s[mt][s8].x), p1 = f2tf(s[mt][s8].y);
                unsigned p2 = f2tf(s[mt][s8].z), p3 = f2tf(s[mt][s8].w);
                unsigned q00 = __shfl_sync(0xffffffffu, p0, src1);
                unsigned q01 = __shfl_sync(0xffffffffu, p1, src1);
                unsigned q10 = __shfl_sync(0xffffffffu, p2, src1);
                unsigned q11 = __shfl_sync(0xffffffffu, p3, src1);
                unsigned q20 = __shfl_sync(0xffffffffu, p0, src2);
                unsigned q21 = __shfl_sync(0xffffffffu, p1, src2);
                unsigned q30 = __shfl_sync(0xffffffffu, p2, src2);
                unsigned q31 = __shfl_sync(0xffffffffu, p3, src2);
                pa[mt][0] = odd ? q01 : q00;
                pa[mt][1] = odd ? q11 : q10;
                pa[mt][2] = odd ? q21 : q20;
                pa[mt][3] = odd ? q31 : q30;
            }
            #pragma unroll
            for (int dn = 0; dn < 8; dn++) {
                unsigned b0 = __float_as_uint(sV[(s8*8 + t)*72     + dn*8 + g]);
                unsigned b1 = __float_as_uint(sV[(s8*8 + t + 4)*72 + dn*8 + g]);
                #pragma unroll
                for (int mt = 0; mt < 2; mt++)
                    mma_tf32(o[mt][dn], pa[mt][0], pa[mt][1], pa[mt][2], pa[mt][3],
                             b0, b1);
            }
        }
    }

    /* epilogue: divide by l, tf32-round, write [b][n][h*d] */
    int b = bh >> 4, h = bh & 15;
    #pragma unroll
    for (int mt = 0; mt < 2; mt++) {
        float inv0 = 1.f / l[mt][0], inv1 = 1.f / l[mt][1];
        int r0 = q0 + wq*32 + mt*16 + g;
        float* ob0 = Out + ((size_t)(b*SEQ + r0))*INNER + h*DH;
        float* ob1 = Out + ((size_t)(b*SEQ + r0 + 8))*INNER + h*DH;
        #pragma unroll
        for (int dn = 0; dn < 8; dn++) {
            int c = dn*8 + 2*t;
            *(float2*)(ob0 + c) = make_float2(f2tff(o[mt][dn].x*inv0), f2tff(o[mt][dn].y*inv0));
            *(float2*)(ob1 + c) = make_float2(f2tff(o[mt][dn].z*inv1), f2tff(o[mt][dn].w*inv1));
        }
    }
}

/* ---------------------------- launch ---------------------------- */
extern "C" void kernel_launch(void* const* d_in, const int* in_sizes, int n_in,
                              void* d_out, int out_size) {
    const float* x    = (const float*)d_in[0];
    const float* pos  = (const float*)d_in[1];
    const float* lnw  = (const float*)d_in[2];
    const float* lnb  = (const float*)d_in[3];
    const float* wqkv = (const float*)d_in[4];
    const float* wout = (const float*)d_in[5];
    float* out = (float*)d_out;

    float *xn, *qkv, *q, *k, *v, *att, *wqr, *wor;
    cudaGetSymbolAddress((void**)&xn,  g_xn);
    cudaGetSymbolAddress((void**)&qkv, g_qkv);
    cudaGetSymbolAddress((void**)&q,   g_q);
    cudaGetSymbolAddress((void**)&k,   g_k);
    cudaGetSymbolAddress((void**)&v,   g_v);
    cudaGetSymbolAddress((void**)&att, g_att);
    cudaGetSymbolAddress((void**)&wqr, g_wqr);
    cudaGetSymbolAddress((void**)&wor, g_wor);

    roundw<<<(DIMX*NQKV/4 + INNER*DIMX/4)/256, 256>>>(wqkv, wout, wqr, wor);
    ln_kernel<<<ROWS, 256>>>(x, lnw, lnb, xn);
    gemm_tf32<<<dim3(NQKV/128, ROWS/128), 256>>>(xn, wqr, qkv, NQKV, DIMX);
    rope_kernel<<<(BATCH*SEQ*HEADS*DH)/256, 256>>>(qkv, pos, q, k, v);
    attn_tc<<<dim3(SEQ/128, BHT), 128>>>(q, k, v, att);
    gemm_tf32<<<dim3(INNER/128, ROWS/128), 256>>>(att, wor, out, INNER, DIMX);
}